// round 7
// baseline (speedup 1.0000x reference)
#include <cuda_runtime.h>
#include <math.h>
#include <cstdint>

#define BB   4
#define RR   64
#define CC   192
#define WNN  16
#define WSZ  16
#define TAPS 9

// ---------------- device scratch ----------------
__device__ float g_t[BB * WNN];
__device__ float g_w[BB * WNN];
__device__ float g_wg[BB * WNN];
// B operand in mma-fragment order: [b][tap][cg][6144 words]
__device__ float g_WeffB[BB * TAPS * 6 * 6144];

__device__ __forceinline__ uint32_t f2tf(float f) {
    uint32_t u; asm("cvt.rna.tf32.f32 %0, %1;" : "=r"(u) : "f"(f)); return u;
}
__device__ __forceinline__ void mma_tf32(float* d, const uint32_t* a, const uint32_t* b) {
    asm volatile(
        "mma.sync.aligned.m16n8k8.row.col.f32.tf32.tf32.f32 "
        "{%0,%1,%2,%3}, {%4,%5,%6,%7}, {%8,%9}, {%0,%1,%2,%3};"
        : "+f"(d[0]), "+f"(d[1]), "+f"(d[2]), "+f"(d[3])
        : "r"(a[0]), "r"(a[1]), "r"(a[2]), "r"(a[3]), "r"(b[0]), "r"(b[1]));
}

// ---------------------------------------------------------------------------
// Kernel A: pooled depthwise stats -> downchannel logits (validated)
// ---------------------------------------------------------------------------
__global__ void kA(const float* __restrict__ x, const float* __restrict__ k1,
                   const float* __restrict__ dcw, const float* __restrict__ dcb) {
    int b   = blockIdx.x >> 4;
    int win = blockIdx.x & 15;
    int c   = threadIdx.x;
    int rb  = win >> 2, cb = win & 3;
    const float* xp = x + ((size_t)b * RR * RR) * CC + c;
    int base = (rb * WSZ) * RR + cb * WSZ;

    float T = 0.f, r0 = 0.f, r15 = 0.f, c0 = 0.f, c15 = 0.f;
    float e00 = 0.f, e0f = 0.f, ef0 = 0.f, eff = 0.f;
    for (int i = 0; i < 16; i++) {
        float rowacc = 0.f, vj0 = 0.f, vj15 = 0.f;
#pragma unroll
        for (int j = 0; j < 16; j++) {
            float v = xp[(size_t)(base + i * RR + j) * CC];
            rowacc += v;
            if (j == 0)  { c0  += v; vj0  = v; }
            if (j == 15) { c15 += v; vj15 = v; }
        }
        T += rowacc;
        if (i == 0)  { r0  = rowacc; e00 = vj0; e0f = vj15; }
        if (i == 15) { r15 = rowacc; ef0 = vj0; eff = vj15; }
    }

    float Rex[3] = { r15, 0.f, r0 };
    float Cex[3] = { c15, 0.f, c0 };
    const float* kp = k1 + (size_t)(win * CC + c) * TAPS;
    float pooled = 0.f;
#pragma unroll
    for (int p = 0; p < 3; p++) {
#pragma unroll
        for (int q = 0; q < 3; q++) {
            float corner = 0.f;
            if (p == 0 && q == 0) corner = eff;
            if (p == 0 && q == 2) corner = ef0;
            if (p == 2 && q == 0) corner = e0f;
            if (p == 2 && q == 2) corner = e00;
            float S = T - Rex[p] - Cex[q] + corner;
            pooled += kp[p * 3 + q] * S;
        }
    }
    pooled *= (1.f / 256.f);
    float contrib = pooled * dcw[win * CC + c];

    __shared__ float red[192];
    red[c] = contrib;
    __syncthreads();
    for (int s = 96; s >= 6; s >>= 1) {
        if (c < s) red[c] += red[c + s];
        __syncthreads();
    }
    if (c == 0) {
        float tot = red[0] + red[1] + red[2] + red[3] + red[4] + red[5];
        g_t[b * WNN + win] = tot + dcb[win];
    }
}

// ---------------------------------------------------------------------------
// Kernel B: tiny MLP (validated)
// ---------------------------------------------------------------------------
__global__ void kB(const float* __restrict__ l1w, const float* __restrict__ l1b,
                   const float* __restrict__ l2w, const float* __restrict__ l2b,
                   const float* __restrict__ gkw) {
    __shared__ float ts[BB * WNN];
    __shared__ float hs[BB * 64];
    int tid = threadIdx.x;
    if (tid < BB * WNN) ts[tid] = g_t[tid];
    __syncthreads();
    {
        int b = tid >> 6, j = tid & 63;
        float a = l1b[j];
#pragma unroll
        for (int s = 0; s < 16; s++) a += ts[b * 16 + s] * l1w[j * 16 + s];
        hs[tid] = 0.5f * a * (1.f + erff(a * 0.70710678118654752f));
    }
    __syncthreads();
    if (tid < BB * WNN) {
        int b = tid >> 4, s = tid & 15;
        float a = l2b[s];
#pragma unroll
        for (int j = 0; j < 64; j++) a += hs[b * 64 + j] * l2w[s * 64 + j];
        float wv = 1.f / (1.f + expf(-a));
        g_w[tid]  = wv;
        g_wg[tid] = wv * gkw[s];
    }
}

// ---------------------------------------------------------------------------
// Kernel W: Weff in mma B-fragment order, tf32-pre-rounded (validated)
// word (per b,tap,cg chunk of 6144):
//   ((n>>3)*4 + (k32>>3))*64 + (n&7)*8 + (k32&3)*2 + ((k32>>2)&1)
// ---------------------------------------------------------------------------
__global__ void __launch_bounds__(192)
kW(const float* __restrict__ k1, const float* __restrict__ gkb,
   const float* __restrict__ fw) {
    int n = blockIdx.x;          // cout
    int c = threadIdx.x;         // cin = k
    __shared__ float sw_[64], swg[64];
    if (c < 64) { sw_[c] = g_w[c]; swg[c] = g_wg[c]; }
    __syncthreads();

    float f[17];
    const float* fp = fw + (size_t)n * ((WNN + 1) * CC) + c;
#pragma unroll
    for (int s = 0; s < 17; s++) f[s] = fp[s * CC];
    float g0 = gkb[0];

    int cg  = c >> 5, k32 = c & 31;
    int wrd = ((n >> 3) * 4 + (k32 >> 3)) * 64 + (n & 7) * 8 +
              (k32 & 3) * 2 + ((k32 >> 2) & 1);

#pragma unroll 1
    for (int tap = 0; tap < 9; tap++) {
        float kv[16];
#pragma unroll
        for (int s = 0; s < 16; s++)
            kv[s] = k1[((size_t)(s * CC + c)) * TAPS + tap];
#pragma unroll
        for (int b = 0; b < 4; b++) {
            float acc = 0.f, ga = g0;
#pragma unroll
            for (int s = 0; s < 16; s++) {
                acc = fmaf(sw_[b * 16 + s] * kv[s], f[s], acc);
                ga  = fmaf(swg[b * 16 + s], kv[s], ga);
            }
            acc = fmaf(ga, f[16], acc);
            g_WeffB[((size_t)(b * 9 + tap) * 6 + cg) * 6144 + wrd] =
                __uint_as_float(f2tf(acc));
        }
    }
}

// ---------------------------------------------------------------------------
// Kernel D: tf32 mma.sync implicit GEMM, 8 warps (2m x 4n, warp = 32m x 48n).
// CTA: M=64 (one image row) x N=192. K = 54 chunks of 32.
// A: gmem->reg->smem fragment-ordered, double buffered.
// B: gmem->registers directly (fragment-ordered); twin m-warps hit L1.
// ---------------------------------------------------------------------------
#define ABUF_W 2048

__global__ void __launch_bounds__(256, 2)
kD(const float* __restrict__ x, const float* __restrict__ fb,
   float* __restrict__ out) {
    __shared__ float smA[2][ABUF_W];

    int tid  = threadIdx.x;
    int lane = tid & 31;
    int wid  = tid >> 5;
    int b    = blockIdx.y;
    int mt   = blockIdx.x;           // image row, pixels [mt*64, mt*64+64)

    const float* xb = x + (size_t)b * RR * RR * CC;
    const float* WB = g_WeffB + (size_t)b * TAPS * 6 * 6144;
    int wm = (wid >> 2) * 2;         // m16-tile base (0 or 2)
    int wn = (wid & 3) * 6;          // n8-tile base

    float acc[2][6][4];
#pragma unroll
    for (int mi = 0; mi < 2; mi++)
#pragma unroll
        for (int ni = 0; ni < 6; ni++)
#pragma unroll
            for (int r = 0; r < 4; r++) acc[mi][ni][r] = 0.f;

    float4   av[2];
    uint32_t bf[6][4][2];

    auto fetchA = [&](int kc) {
        int tap = kc / 6;
        int cbs = (kc - tap * 6) * 32;
        int dy = tap / 3 - 1, dx = tap % 3 - 1;
        int sy = mt + dy;
#pragma unroll
        for (int j = 0; j < 2; j++) {
            int i = tid + 256 * j;
            int m = i >> 3, f = i & 7;
            int sx = m + dx;
            if ((unsigned)sy < RR && (unsigned)sx < RR)
                av[j] = *(const float4*)(xb + ((size_t)(sy * RR + sx)) * CC + cbs + f * 4);
            else
                av[j] = make_float4(0.f, 0.f, 0.f, 0.f);
        }
    };
    auto storeA = [&](float* buf) {
#pragma unroll
        for (int j = 0; j < 2; j++) {
            int i = tid + 256 * j;
            int m = i >> 3, f = i & 7;
            int q  = ((m >> 4) << 2) + (f >> 1);
            int rb = ((f & 1) << 1) | ((m >> 3) & 1);
            float* p = buf + q * 128 + (m & 7) * 16 + rb;
            p[0]  = __uint_as_float(f2tf(av[j].x));
            p[4]  = __uint_as_float(f2tf(av[j].y));
            p[8]  = __uint_as_float(f2tf(av[j].z));
            p[12] = __uint_as_float(f2tf(av[j].w));
        }
    };
    auto loadB = [&](int kc) {
        int tap = kc / 6, cg = kc - tap * 6;
        const float* src = WB + ((size_t)tap * 6 + cg) * 6144;
#pragma unroll
        for (int ni = 0; ni < 6; ni++)
#pragma unroll
            for (int ks = 0; ks < 4; ks++) {
                float2 v = *(const float2*)(src + ((wn + ni) * 4 + ks) * 64 + lane * 2);
                bf[ni][ks][0] = __float_as_uint(v.x);
                bf[ni][ks][1] = __float_as_uint(v.y);
            }
    };

    // ---- prologue ----
    loadB(0);
    fetchA(0);
    storeA(smA[0]);
    __syncthreads();

#pragma unroll 1
    for (int kc = 0; kc < 54; kc++) {
        if (kc < 53) fetchA(kc + 1);        // long-latency LDG first

        const float* bufA = smA[kc & 1];
#pragma unroll
        for (int ks = 0; ks < 4; ks++) {
            uint32_t af[2][4];
#pragma unroll
            for (int mi = 0; mi < 2; mi++) {
                float4 v = *(const float4*)(bufA + ((wm + mi) * 4 + ks) * 128 + lane * 4);
                af[mi][0] = __float_as_uint(v.x);
                af[mi][1] = __float_as_uint(v.y);
                af[mi][2] = __float_as_uint(v.z);
                af[mi][3] = __float_as_uint(v.w);
            }
#pragma unroll
            for (int mi = 0; mi < 2; mi++)
#pragma unroll
                for (int ni = 0; ni < 6; ni++)
                    mma_tf32(acc[mi][ni], af[mi], bf[ni][ks]);
        }

        if (kc < 53) {
            loadB(kc + 1);                  // refill B regs for next chunk
            storeA(smA[(kc + 1) & 1]);
        }
        __syncthreads();
    }

    // ---- epilogue: +bias, STG.64 ----
#pragma unroll
    for (int ni = 0; ni < 6; ni++) {
        int co = (wid & 3) * 48 + ni * 8 + (lane & 3) * 2;
        float bx = fb[co], by = fb[co + 1];
#pragma unroll
        for (int mi = 0; mi < 2; mi++) {
            int m0 = mt * 64 + (wm + mi) * 16 + (lane >> 2);
            size_t o0 = ((size_t)b * RR * RR + m0) * CC + co;
            *(float2*)(out + o0) =
                make_float2(acc[mi][ni][0] + bx, acc[mi][ni][1] + by);
            *(float2*)(out + o0 + (size_t)8 * CC) =
                make_float2(acc[mi][ni][2] + bx, acc[mi][ni][3] + by);
        }
    }
}

// ---------------------------------------------------------------------------
extern "C" void kernel_launch(void* const* d_in, const int* in_sizes, int n_in,
                              void* d_out, int out_size) {
    const float* x   = (const float*)d_in[0];
    const float* k1  = (const float*)d_in[1];
    const float* dcw = (const float*)d_in[2];
    const float* dcb = (const float*)d_in[3];
    const float* l1w = (const float*)d_in[4];
    const float* l1b = (const float*)d_in[5];
    const float* l2w = (const float*)d_in[6];
    const float* l2b = (const float*)d_in[7];
    const float* gkw = (const float*)d_in[8];
    const float* gkb = (const float*)d_in[9];
    const float* fw  = (const float*)d_in[10];
    const float* fb  = (const float*)d_in[11];
    float* out = (float*)d_out;

    kA<<<BB * WNN, CC>>>(x, k1, dcw, dcb);
    kB<<<1, 256>>>(l1w, l1b, l2w, l2b, gkw);
    kW<<<CC, CC>>>(k1, gkb, fw);
    dim3 g(RR, BB);   // 64 row-tiles x 4 batches = 256 CTAs
    kD<<<g, 256>>>(x, fb, out);
}

// round 8
// speedup vs baseline: 1.0348x; 1.0348x over previous
#include <cuda_runtime.h>
#include <math.h>
#include <cstdint>

#define BB   4
#define RR   64
#define CC   192
#define WNN  16
#define WSZ  16
#define TAPS 9

// ---------------- device scratch ----------------
__device__ float g_t[BB * WNN];
__device__ float g_w[BB * WNN];
__device__ float g_wg[BB * WNN];
__device__ float g_WeffB[BB * TAPS * 6 * 6144];   // B in mma-fragment order
__device__ float g_xtf[BB * RR * RR * CC];        // x pre-rounded to tf32

__device__ __forceinline__ uint32_t f2tf(float f) {
    uint32_t u; asm("cvt.rna.tf32.f32 %0, %1;" : "=r"(u) : "f"(f)); return u;
}
__device__ __forceinline__ uint32_t smem_u32(const void* p) {
    uint32_t a;
    asm("{ .reg .u64 t; cvta.to.shared.u64 t, %1; cvt.u32.u64 %0, t; }"
        : "=r"(a) : "l"(p));
    return a;
}
__device__ __forceinline__ void mma_tf32(float* d, const uint32_t* a, const uint32_t* b) {
    asm volatile(
        "mma.sync.aligned.m16n8k8.row.col.f32.tf32.tf32.f32 "
        "{%0,%1,%2,%3}, {%4,%5,%6,%7}, {%8,%9}, {%0,%1,%2,%3};"
        : "+f"(d[0]), "+f"(d[1]), "+f"(d[2]), "+f"(d[3])
        : "r"(a[0]), "r"(a[1]), "r"(a[2]), "r"(a[3]), "r"(b[0]), "r"(b[1]));
}
#define CP_COMMIT() asm volatile("cp.async.commit_group;" ::: "memory")
#define CP_WAIT(n)  asm volatile("cp.async.wait_group %0;" :: "n"(n) : "memory")

// ---------------------------------------------------------------------------
// Kernel X: pre-round x to tf32 (read once, write once)
// ---------------------------------------------------------------------------
__global__ void kX(const float* __restrict__ x, int n) {
    int i = blockIdx.x * 256 + threadIdx.x;
    if (i < n) g_xtf[i] = __uint_as_float(f2tf(x[i]));
}

// ---------------------------------------------------------------------------
// Kernel A: pooled depthwise stats -> downchannel logits (validated)
// ---------------------------------------------------------------------------
__global__ void kA(const float* __restrict__ x, const float* __restrict__ k1,
                   const float* __restrict__ dcw, const float* __restrict__ dcb) {
    int b   = blockIdx.x >> 4;
    int win = blockIdx.x & 15;
    int c   = threadIdx.x;
    int rb  = win >> 2, cb = win & 3;
    const float* xp = x + ((size_t)b * RR * RR) * CC + c;
    int base = (rb * WSZ) * RR + cb * WSZ;

    float T = 0.f, r0 = 0.f, r15 = 0.f, c0 = 0.f, c15 = 0.f;
    float e00 = 0.f, e0f = 0.f, ef0 = 0.f, eff = 0.f;
    for (int i = 0; i < 16; i++) {
        float rowacc = 0.f, vj0 = 0.f, vj15 = 0.f;
#pragma unroll
        for (int j = 0; j < 16; j++) {
            float v = xp[(size_t)(base + i * RR + j) * CC];
            rowacc += v;
            if (j == 0)  { c0  += v; vj0  = v; }
            if (j == 15) { c15 += v; vj15 = v; }
        }
        T += rowacc;
        if (i == 0)  { r0  = rowacc; e00 = vj0; e0f = vj15; }
        if (i == 15) { r15 = rowacc; ef0 = vj0; eff = vj15; }
    }

    float Rex[3] = { r15, 0.f, r0 };
    float Cex[3] = { c15, 0.f, c0 };
    const float* kp = k1 + (size_t)(win * CC + c) * TAPS;
    float pooled = 0.f;
#pragma unroll
    for (int p = 0; p < 3; p++) {
#pragma unroll
        for (int q = 0; q < 3; q++) {
            float corner = 0.f;
            if (p == 0 && q == 0) corner = eff;
            if (p == 0 && q == 2) corner = ef0;
            if (p == 2 && q == 0) corner = e0f;
            if (p == 2 && q == 2) corner = e00;
            float S = T - Rex[p] - Cex[q] + corner;
            pooled += kp[p * 3 + q] * S;
        }
    }
    pooled *= (1.f / 256.f);
    float contrib = pooled * dcw[win * CC + c];

    __shared__ float red[192];
    red[c] = contrib;
    __syncthreads();
    for (int s = 96; s >= 6; s >>= 1) {
        if (c < s) red[c] += red[c + s];
        __syncthreads();
    }
    if (c == 0) {
        float tot = red[0] + red[1] + red[2] + red[3] + red[4] + red[5];
        g_t[b * WNN + win] = tot + dcb[win];
    }
}

// ---------------------------------------------------------------------------
// Kernel B: tiny MLP (validated)
// ---------------------------------------------------------------------------
__global__ void kB(const float* __restrict__ l1w, const float* __restrict__ l1b,
                   const float* __restrict__ l2w, const float* __restrict__ l2b,
                   const float* __restrict__ gkw) {
    __shared__ float ts[BB * WNN];
    __shared__ float hs[BB * 64];
    int tid = threadIdx.x;
    if (tid < BB * WNN) ts[tid] = g_t[tid];
    __syncthreads();
    {
        int b = tid >> 6, j = tid & 63;
        float a = l1b[j];
#pragma unroll
        for (int s = 0; s < 16; s++) a += ts[b * 16 + s] * l1w[j * 16 + s];
        hs[tid] = 0.5f * a * (1.f + erff(a * 0.70710678118654752f));
    }
    __syncthreads();
    if (tid < BB * WNN) {
        int b = tid >> 4, s = tid & 15;
        float a = l2b[s];
#pragma unroll
        for (int j = 0; j < 64; j++) a += hs[b * 64 + j] * l2w[s * 64 + j];
        float wv = 1.f / (1.f + expf(-a));
        g_w[tid]  = wv;
        g_wg[tid] = wv * gkw[s];
    }
}

// ---------------------------------------------------------------------------
// Kernel W: Weff in mma B-fragment order, tf32-pre-rounded (validated)
// ---------------------------------------------------------------------------
__global__ void __launch_bounds__(192)
kW(const float* __restrict__ k1, const float* __restrict__ gkb,
   const float* __restrict__ fw) {
    int n = blockIdx.x;          // cout
    int c = threadIdx.x;         // cin = k
    __shared__ float sw_[64], swg[64];
    if (c < 64) { sw_[c] = g_w[c]; swg[c] = g_wg[c]; }
    __syncthreads();

    float f[17];
    const float* fp = fw + (size_t)n * ((WNN + 1) * CC) + c;
#pragma unroll
    for (int s = 0; s < 17; s++) f[s] = fp[s * CC];
    float g0 = gkb[0];

    int cg  = c >> 5, k32 = c & 31;
    int wrd = ((n >> 3) * 4 + (k32 >> 3)) * 64 + (n & 7) * 8 +
              (k32 & 3) * 2 + ((k32 >> 2) & 1);

#pragma unroll 1
    for (int tap = 0; tap < 9; tap++) {
        float kv[16];
#pragma unroll
        for (int s = 0; s < 16; s++)
            kv[s] = k1[((size_t)(s * CC + c)) * TAPS + tap];
#pragma unroll
        for (int b = 0; b < 4; b++) {
            float acc = 0.f, ga = g0;
#pragma unroll
            for (int s = 0; s < 16; s++) {
                acc = fmaf(sw_[b * 16 + s] * kv[s], f[s], acc);
                ga  = fmaf(swg[b * 16 + s], kv[s], ga);
            }
            acc = fmaf(ga, f[16], acc);
            g_WeffB[((size_t)(b * 9 + tap) * 6 + cg) * 6144 + wrd] =
                __uint_as_float(f2tf(acc));
        }
    }
}

// ---------------------------------------------------------------------------
// Kernel D: tf32 mma.sync implicit GEMM, 4 fat warps (warp = 64m x 48n).
// CTA: M=64 x N=192, K = 54 chunks of 32.
// A: cp.async 3-stage pipeline into padded smem [f][m][4] (f-row = 260 words).
// B: direct LDG into double-buffered registers, prefetched 1 chunk ahead.
// ---------------------------------------------------------------------------
#define FROW 260                       // 64 pixels * 4 + 4 pad words
#define STGW (8 * FROW)                // 2080 words per stage

__global__ void __launch_bounds__(128, 2)
kD(const float* __restrict__ fb, float* __restrict__ out) {
    __shared__ float smA[3][STGW];

    int tid  = threadIdx.x;
    int lane = tid & 31;
    int wid  = tid >> 5;
    int b    = blockIdx.y;
    int mt   = blockIdx.x;             // image row

    const float* xtf = g_xtf + (size_t)b * RR * RR * CC;
    const float* WB  = g_WeffB + (size_t)b * TAPS * 6 * 6144;
    int wn = wid * 6;

    float acc[4][6][4];
#pragma unroll
    for (int mi = 0; mi < 4; mi++)
#pragma unroll
        for (int ni = 0; ni < 6; ni++)
#pragma unroll
            for (int r = 0; r < 4; r++) acc[mi][ni][r] = 0.f;

    uint32_t bfA[6][4][2], bfB[6][4][2];

    auto stageA = [&](int kc, int stg) {
        int tap = kc / 6;
        int cbs = (kc - tap * 6) * 32;
        int dy = tap / 3 - 1, dx = tap % 3 - 1;
        int sy = mt + dy;
        uint32_t dbase = smem_u32(&smA[stg][0]);
#pragma unroll
        for (int j = 0; j < 4; j++) {
            int idx = tid + 128 * j;
            int m = idx >> 3, f = idx & 7;
            int sx = m + dx;
            bool ok = ((unsigned)sy < RR) && ((unsigned)sx < RR);
            const float* src = ok ? (xtf + ((size_t)(sy * RR + sx)) * CC + cbs + f * 4)
                                  : xtf;
            uint32_t dst = dbase + (uint32_t)(f * FROW + m * 4) * 4;
            int ssz = ok ? 16 : 0;
            asm volatile("cp.async.ca.shared.global [%0], [%1], 16, %2;"
                         :: "r"(dst), "l"(src), "r"(ssz));
        }
    };
    auto loadB = [&](int kc, uint32_t (&bf)[6][4][2]) {
        int tap = kc / 6, cg = kc - tap * 6;
        const float* src = WB + ((size_t)tap * 6 + cg) * 6144;
#pragma unroll
        for (int ni = 0; ni < 6; ni++)
#pragma unroll
            for (int ks = 0; ks < 4; ks++) {
                float2 v = *(const float2*)(src + ((wn + ni) * 4 + ks) * 64 + lane * 2);
                bf[ni][ks][0] = __float_as_uint(v.x);
                bf[ni][ks][1] = __float_as_uint(v.y);
            }
    };
    int r4 = (lane >> 2) * 4 + (lane & 3);
    auto compute = [&](int kc, uint32_t (&bf)[6][4][2]) {
        const float* fr = smA[kc % 3];
#pragma unroll
        for (int ks = 0; ks < 4; ks++) {
            uint32_t af[4][4];
#pragma unroll
            for (int mi = 0; mi < 4; mi++) {
                const float* p = fr + ks * (2 * FROW) + mi * 64 + r4;
                af[mi][0] = __float_as_uint(p[0]);
                af[mi][1] = __float_as_uint(p[32]);
                af[mi][2] = __float_as_uint(p[FROW]);
                af[mi][3] = __float_as_uint(p[FROW + 32]);
            }
#pragma unroll
            for (int mi = 0; mi < 4; mi++)
#pragma unroll
                for (int ni = 0; ni < 6; ni++)
                    mma_tf32(acc[mi][ni], af[mi], bf[ni][ks]);
        }
    };

    // ---- prologue ----
    stageA(0, 0); CP_COMMIT();
    stageA(1, 1); CP_COMMIT();
    loadB(0, bfA);

#pragma unroll 1
    for (int it = 0; it < 27; it++) {
        int kc = it * 2;
        // ---- chunk kc ----
        if (kc < 52) CP_WAIT(1); else CP_WAIT(0);
        __syncthreads();
        if (kc + 2 < 54) { stageA(kc + 2, (kc + 2) % 3); CP_COMMIT(); }
        loadB(kc + 1, bfB);
        compute(kc, bfA);
        // ---- chunk kc+1 ----
        if (kc + 1 < 52) CP_WAIT(1); else CP_WAIT(0);
        __syncthreads();
        if (kc + 3 < 54) { stageA(kc + 3, (kc + 3) % 3); CP_COMMIT(); }
        if (kc + 2 < 54) loadB(kc + 2, bfA);
        compute(kc + 1, bfB);
    }

    // ---- epilogue: +bias, STG.64 ----
#pragma unroll
    for (int ni = 0; ni < 6; ni++) {
        int co = wid * 48 + ni * 8 + (lane & 3) * 2;
        float bx = fb[co], by = fb[co + 1];
#pragma unroll
        for (int mi = 0; mi < 4; mi++) {
            int m0 = mt * 64 + mi * 16 + (lane >> 2);
            size_t o0 = ((size_t)b * RR * RR + m0) * CC + co;
            *(float2*)(out + o0) =
                make_float2(acc[mi][ni][0] + bx, acc[mi][ni][1] + by);
            *(float2*)(out + o0 + (size_t)8 * CC) =
                make_float2(acc[mi][ni][2] + bx, acc[mi][ni][3] + by);
        }
    }
}

// ---------------------------------------------------------------------------
extern "C" void kernel_launch(void* const* d_in, const int* in_sizes, int n_in,
                              void* d_out, int out_size) {
    const float* x   = (const float*)d_in[0];
    const float* k1  = (const float*)d_in[1];
    const float* dcw = (const float*)d_in[2];
    const float* dcb = (const float*)d_in[3];
    const float* l1w = (const float*)d_in[4];
    const float* l1b = (const float*)d_in[5];
    const float* l2w = (const float*)d_in[6];
    const float* l2b = (const float*)d_in[7];
    const float* gkw = (const float*)d_in[8];
    const float* gkb = (const float*)d_in[9];
    const float* fw  = (const float*)d_in[10];
    const float* fb  = (const float*)d_in[11];
    float* out = (float*)d_out;

    int nx = BB * RR * RR * CC;
    kX<<<(nx + 255) / 256, 256>>>(x, nx);
    kA<<<BB * WNN, CC>>>(x, k1, dcw, dcb);
    kB<<<1, 256>>>(l1w, l1b, l2w, l2b, gkw);
    kW<<<CC, CC>>>(k1, gkb, fw);
    dim3 g(RR, BB);   // 64 row-tiles x 4 batches = 256 CTAs
    kD<<<g, 128>>>(fb, out);
}

// round 9
// speedup vs baseline: 1.0361x; 1.0012x over previous
#include <cuda_runtime.h>
#include <math.h>
#include <cstdint>

#define BB   4
#define RR   64
#define CC   192
#define WNN  16
#define WSZ  16
#define TAPS 9

// ---------------- device scratch ----------------
__device__ float g_t[BB * WNN];
__device__ float g_w[BB * WNN];
__device__ float g_wg[BB * WNN];
__device__ float g_WeffB[BB * TAPS * 6 * 6144];       // B in mma-fragment order
__device__ float g_xA[(size_t)BB * 3 * RR * 6 * 2048]; // A frag-order, 3 dx shifts
__device__ float g_k1T[TAPS * WNN * CC];               // k1 transposed [tap][s][c]

__device__ __forceinline__ uint32_t f2tf(float f) {
    uint32_t u; asm("cvt.rna.tf32.f32 %0, %1;" : "=r"(u) : "f"(f)); return u;
}
__device__ __forceinline__ void mma_tf32(float* d, const uint32_t* a, const uint32_t* b) {
    asm volatile(
        "mma.sync.aligned.m16n8k8.row.col.f32.tf32.tf32.f32 "
        "{%0,%1,%2,%3}, {%4,%5,%6,%7}, {%8,%9}, {%0,%1,%2,%3};"
        : "+f"(d[0]), "+f"(d[1]), "+f"(d[2]), "+f"(d[3])
        : "r"(a[0]), "r"(a[1]), "r"(a[2]), "r"(a[3]), "r"(b[0]), "r"(b[1]));
}

// ---------------------------------------------------------------------------
// Kernel X: build A operand in mma-fragment order, tf32-rounded, for the
// 3 column shifts dx-1. Block = (sy, dxi, b); warp-unit = (cg, ks, mi).
// Fragment word (lane, r): m = mi*16 + (lane>>2) + ((r&1)<<3),
//                          k8 = (lane&3) + ((r>>1)<<2).
// ---------------------------------------------------------------------------
__global__ void __launch_bounds__(256)
kX(const float* __restrict__ x) {
    int sy  = blockIdx.x;
    int dxi = blockIdx.y;
    int b   = blockIdx.z;
    int wid  = threadIdx.x >> 5;
    int lane = threadIdx.x & 31;

    int px = lane >> 1;                 // 0..15
    int kk = (lane & 1) * 4;            // 0 or 4

    const float* xr = x + ((size_t)(b * RR + sy) * RR) * CC;

#pragma unroll 1
    for (int u = wid; u < 96; u += 8) {
        int cg = u >> 4;                // 0..5
        int ks = (u >> 2) & 3;          // 0..3
        int mi = u & 3;                 // 0..3
        int sx = mi * 16 + px + dxi - 1;

        float4 v = make_float4(0.f, 0.f, 0.f, 0.f);
        if ((unsigned)sx < RR)
            v = *(const float4*)(xr + (size_t)sx * CC + cg * 32 + ks * 8 + kk);

        float* dst = g_xA + ((((size_t)b * 3 + dxi) * RR + sy) * 6 + cg) * 2048
                         + (ks * 4 + mi) * 128;
        int rbase = (kk >> 2) * 2 + (px >> 3);
        uint32_t vv[4] = { f2tf(v.x), f2tf(v.y), f2tf(v.z), f2tf(v.w) };
#pragma unroll
        for (int i = 0; i < 4; i++)
            dst[((px & 7) * 4 + i) * 4 + rbase] = __uint_as_float(vv[i]);
    }
}

// ---------------------------------------------------------------------------
// Kernel T: transpose conv1_w for coalesced kW reads.
// ---------------------------------------------------------------------------
__global__ void kT(const float* __restrict__ k1) {
    int i = blockIdx.x * 256 + threadIdx.x;
    if (i >= TAPS * WNN * CC) return;
    int tap = i / (WNN * CC);
    int rc  = i - tap * (WNN * CC);
    g_k1T[i] = k1[(size_t)rc * TAPS + tap];
}

// ---------------------------------------------------------------------------
// Kernel A: pooled depthwise stats -> downchannel logits (validated)
// ---------------------------------------------------------------------------
__global__ void kA(const float* __restrict__ x, const float* __restrict__ k1,
                   const float* __restrict__ dcw, const float* __restrict__ dcb) {
    int b   = blockIdx.x >> 4;
    int win = blockIdx.x & 15;
    int c   = threadIdx.x;
    int rb  = win >> 2, cb = win & 3;
    const float* xp = x + ((size_t)b * RR * RR) * CC + c;
    int base = (rb * WSZ) * RR + cb * WSZ;

    float T = 0.f, r0 = 0.f, r15 = 0.f, c0 = 0.f, c15 = 0.f;
    float e00 = 0.f, e0f = 0.f, ef0 = 0.f, eff = 0.f;
    for (int i = 0; i < 16; i++) {
        float rowacc = 0.f, vj0 = 0.f, vj15 = 0.f;
#pragma unroll
        for (int j = 0; j < 16; j++) {
            float v = xp[(size_t)(base + i * RR + j) * CC];
            rowacc += v;
            if (j == 0)  { c0  += v; vj0  = v; }
            if (j == 15) { c15 += v; vj15 = v; }
        }
        T += rowacc;
        if (i == 0)  { r0  = rowacc; e00 = vj0; e0f = vj15; }
        if (i == 15) { r15 = rowacc; ef0 = vj0; eff = vj15; }
    }

    float Rex[3] = { r15, 0.f, r0 };
    float Cex[3] = { c15, 0.f, c0 };
    const float* kp = k1 + (size_t)(win * CC + c) * TAPS;
    float pooled = 0.f;
#pragma unroll
    for (int p = 0; p < 3; p++) {
#pragma unroll
        for (int q = 0; q < 3; q++) {
            float corner = 0.f;
            if (p == 0 && q == 0) corner = eff;
            if (p == 0 && q == 2) corner = ef0;
            if (p == 2 && q == 0) corner = e0f;
            if (p == 2 && q == 2) corner = e00;
            float S = T - Rex[p] - Cex[q] + corner;
            pooled += kp[p * 3 + q] * S;
        }
    }
    pooled *= (1.f / 256.f);
    float contrib = pooled * dcw[win * CC + c];

    __shared__ float red[192];
    red[c] = contrib;
    __syncthreads();
    for (int s = 96; s >= 6; s >>= 1) {
        if (c < s) red[c] += red[c + s];
        __syncthreads();
    }
    if (c == 0) {
        float tot = red[0] + red[1] + red[2] + red[3] + red[4] + red[5];
        g_t[b * WNN + win] = tot + dcb[win];
    }
}

// ---------------------------------------------------------------------------
// Kernel B: tiny MLP (validated)
// ---------------------------------------------------------------------------
__global__ void kB(const float* __restrict__ l1w, const float* __restrict__ l1b,
                   const float* __restrict__ l2w, const float* __restrict__ l2b,
                   const float* __restrict__ gkw) {
    __shared__ float ts[BB * WNN];
    __shared__ float hs[BB * 64];
    int tid = threadIdx.x;
    if (tid < BB * WNN) ts[tid] = g_t[tid];
    __syncthreads();
    {
        int b = tid >> 6, j = tid & 63;
        float a = l1b[j];
#pragma unroll
        for (int s = 0; s < 16; s++) a += ts[b * 16 + s] * l1w[j * 16 + s];
        hs[tid] = 0.5f * a * (1.f + erff(a * 0.70710678118654752f));
    }
    __syncthreads();
    if (tid < BB * WNN) {
        int b = tid >> 4, s = tid & 15;
        float a = l2b[s];
#pragma unroll
        for (int j = 0; j < 64; j++) a += hs[b * 64 + j] * l2w[s * 64 + j];
        float wv = 1.f / (1.f + expf(-a));
        g_w[tid]  = wv;
        g_wg[tid] = wv * gkw[s];
    }
}

// ---------------------------------------------------------------------------
// Kernel W: Weff in mma B-fragment order (reads coalesced g_k1T).
// ---------------------------------------------------------------------------
__global__ void __launch_bounds__(192)
kW(const float* __restrict__ gkb, const float* __restrict__ fw) {
    int n = blockIdx.x;          // cout
    int c = threadIdx.x;         // cin = k
    __shared__ float sw_[64], swg[64];
    if (c < 64) { sw_[c] = g_w[c]; swg[c] = g_wg[c]; }
    __syncthreads();

    float f[17];
    const float* fp = fw + (size_t)n * ((WNN + 1) * CC) + c;
#pragma unroll
    for (int s = 0; s < 17; s++) f[s] = fp[s * CC];
    float g0 = gkb[0];

    int cg  = c >> 5, k32 = c & 31;
    int wrd = ((n >> 3) * 4 + (k32 >> 3)) * 64 + (n & 7) * 8 +
              (k32 & 3) * 2 + ((k32 >> 2) & 1);

#pragma unroll 1
    for (int tap = 0; tap < 9; tap++) {
        float kv[16];
        const float* kt = g_k1T + (size_t)tap * WNN * CC + c;
#pragma unroll
        for (int s = 0; s < 16; s++) kv[s] = kt[s * CC];
#pragma unroll
        for (int b = 0; b < 4; b++) {
            float acc = 0.f, ga = g0;
#pragma unroll
            for (int s = 0; s < 16; s++) {
                acc = fmaf(sw_[b * 16 + s] * kv[s], f[s], acc);
                ga  = fmaf(swg[b * 16 + s], kv[s], ga);
            }
            acc = fmaf(ga, f[16], acc);
            g_WeffB[((size_t)(b * 9 + tap) * 6 + cg) * 6144 + wrd] =
                __uint_as_float(f2tf(acc));
        }
    }
}

// ---------------------------------------------------------------------------
// Kernel D: tf32 mma.sync implicit GEMM, 4 fat warps (warp = 64m x 48n).
// NO smem, NO barriers: A and B both loaded straight to registers from
// fragment-ordered gmem. B double-buffered (L2 latency), A per-ks (L1 hits:
// all 4 warps read identical A addresses).
// ---------------------------------------------------------------------------
__global__ void __launch_bounds__(128, 2)
kD(const float* __restrict__ fb, float* __restrict__ out) {
    int tid  = threadIdx.x;
    int lane = tid & 31;
    int wid  = tid >> 5;
    int b    = blockIdx.y;
    int mt   = blockIdx.x;             // image row

    const float* WB = g_WeffB + (size_t)b * TAPS * 6 * 6144;
    int wn = wid * 6;

    float acc[4][6][4];
#pragma unroll
    for (int mi = 0; mi < 4; mi++)
#pragma unroll
        for (int ni = 0; ni < 6; ni++)
#pragma unroll
            for (int r = 0; r < 4; r++) acc[mi][ni][r] = 0.f;

    uint32_t bfA[6][4][2], bfB[6][4][2];

    auto loadB = [&](int kc, uint32_t (&bf)[6][4][2]) {
        int tap = kc / 6, cg = kc - tap * 6;
        const float* src = WB + ((size_t)tap * 6 + cg) * 6144;
#pragma unroll
        for (int ni = 0; ni < 6; ni++)
#pragma unroll
            for (int ks = 0; ks < 4; ks++) {
                float2 v = *(const float2*)(src + ((wn + ni) * 4 + ks) * 64 + lane * 2);
                bf[ni][ks][0] = __float_as_uint(v.x);
                bf[ni][ks][1] = __float_as_uint(v.y);
            }
    };
    auto computeChunk = [&](int kc, uint32_t (&bf)[6][4][2]) {
        int tap = kc / 6, cg = kc - tap * 6;
        int dy = tap / 3 - 1, dxi = tap % 3;
        int sy = mt + dy;
        if ((unsigned)sy >= RR) return;          // zero A -> no contribution
        const float* base = g_xA +
            ((((size_t)b * 3 + dxi) * RR + sy) * 6 + cg) * 2048;
#pragma unroll
        for (int ks = 0; ks < 4; ks++) {
            uint32_t af[4][4];
#pragma unroll
            for (int mi = 0; mi < 4; mi++) {
                float4 v = *(const float4*)(base + (ks * 4 + mi) * 128 + lane * 4);
                af[mi][0] = __float_as_uint(v.x);
                af[mi][1] = __float_as_uint(v.y);
                af[mi][2] = __float_as_uint(v.z);
                af[mi][3] = __float_as_uint(v.w);
            }
#pragma unroll
            for (int mi = 0; mi < 4; mi++)
#pragma unroll
                for (int ni = 0; ni < 6; ni++)
                    mma_tf32(acc[mi][ni], af[mi], bf[ni][ks]);
        }
    };

    loadB(0, bfA);
#pragma unroll 1
    for (int it = 0; it < 27; it++) {
        int kc = it * 2;
        loadB(kc + 1, bfB);
        computeChunk(kc, bfA);
        if (kc + 2 < 54) loadB(kc + 2, bfA);
        computeChunk(kc + 1, bfB);
    }

    // ---- epilogue: +bias, STG.64 ----
#pragma unroll
    for (int ni = 0; ni < 6; ni++) {
        int co = wid * 48 + ni * 8 + (lane & 3) * 2;
        float bx = fb[co], by = fb[co + 1];
#pragma unroll
        for (int mi = 0; mi < 4; mi++) {
            int m0 = mt * 64 + mi * 16 + (lane >> 2);
            size_t o0 = ((size_t)b * RR * RR + m0) * CC + co;
            *(float2*)(out + o0) =
                make_float2(acc[mi][ni][0] + bx, acc[mi][ni][1] + by);
            *(float2*)(out + o0 + (size_t)8 * CC) =
                make_float2(acc[mi][ni][2] + bx, acc[mi][ni][3] + by);
        }
    }
}

// ---------------------------------------------------------------------------
extern "C" void kernel_launch(void* const* d_in, const int* in_sizes, int n_in,
                              void* d_out, int out_size) {
    const float* x   = (const float*)d_in[0];
    const float* k1  = (const float*)d_in[1];
    const float* dcw = (const float*)d_in[2];
    const float* dcb = (const float*)d_in[3];
    const float* l1w = (const float*)d_in[4];
    const float* l1b = (const float*)d_in[5];
    const float* l2w = (const float*)d_in[6];
    const float* l2b = (const float*)d_in[7];
    const float* gkw = (const float*)d_in[8];
    const float* gkb = (const float*)d_in[9];
    const float* fw  = (const float*)d_in[10];
    const float* fb  = (const float*)d_in[11];
    float* out = (float*)d_out;

    kX<<<dim3(RR, 3, BB), 256>>>(x);
    kT<<<(TAPS * WNN * CC + 255) / 256, 256>>>(k1);
    kA<<<BB * WNN, CC>>>(x, k1, dcw, dcb);
    kB<<<1, 256>>>(l1w, l1b, l2w, l2b, gkw);
    kW<<<CC, CC>>>(gkb, fw);
    dim3 g(RR, BB);
    kD<<<g, 128>>>(fb, out);
}

// round 10
// speedup vs baseline: 1.0504x; 1.0139x over previous
#include <cuda_runtime.h>
#include <math.h>
#include <cstdint>

#define BB   4
#define RR   64
#define CC   192
#define WNN  16
#define WSZ  16
#define TAPS 9

// ---------------- device scratch ----------------
__device__ float g_t[BB * WNN];
__device__ float g_WeffB[BB * TAPS * 6 * 6144];        // B in mma-fragment order
__device__ float g_xA[(size_t)BB * 3 * RR * 6 * 2048]; // A frag-order, 3 dx shifts
__device__ float g_k1T[TAPS * WNN * CC];               // k1 transposed [tap][s][c]

__device__ __forceinline__ uint32_t f2tf(float f) {
    uint32_t u; asm("cvt.rna.tf32.f32 %0, %1;" : "=r"(u) : "f"(f)); return u;
}
__device__ __forceinline__ void mma_tf32(float* d, const uint32_t* a, const uint32_t* b) {
    asm volatile(
        "mma.sync.aligned.m16n8k8.row.col.f32.tf32.tf32.f32 "
        "{%0,%1,%2,%3}, {%4,%5,%6,%7}, {%8,%9}, {%0,%1,%2,%3};"
        : "+f"(d[0]), "+f"(d[1]), "+f"(d[2]), "+f"(d[3])
        : "r"(a[0]), "r"(a[1]), "r"(a[2]), "r"(a[3]), "r"(b[0]), "r"(b[1]));
}

// ---------------------------------------------------------------------------
// Kernel X: build A operand in mma-fragment order, tf32-rounded (validated)
// ---------------------------------------------------------------------------
__global__ void __launch_bounds__(256)
kX(const float* __restrict__ x) {
    int sy  = blockIdx.x;
    int dxi = blockIdx.y;
    int b   = blockIdx.z;
    int wid  = threadIdx.x >> 5;
    int lane = threadIdx.x & 31;

    int px = lane >> 1;
    int kk = (lane & 1) * 4;

    const float* xr = x + ((size_t)(b * RR + sy) * RR) * CC;

#pragma unroll 1
    for (int u = wid; u < 96; u += 8) {
        int cg = u >> 4;
        int ks = (u >> 2) & 3;
        int mi = u & 3;
        int sx = mi * 16 + px + dxi - 1;

        float4 v = make_float4(0.f, 0.f, 0.f, 0.f);
        if ((unsigned)sx < RR)
            v = *(const float4*)(xr + (size_t)sx * CC + cg * 32 + ks * 8 + kk);

        float* dst = g_xA + ((((size_t)b * 3 + dxi) * RR + sy) * 6 + cg) * 2048
                         + (ks * 4 + mi) * 128;
        int rbase = (kk >> 2) * 2 + (px >> 3);
        uint32_t vv[4] = { f2tf(v.x), f2tf(v.y), f2tf(v.z), f2tf(v.w) };
#pragma unroll
        for (int i = 0; i < 4; i++)
            dst[((px & 7) * 4 + i) * 4 + rbase] = __uint_as_float(vv[i]);
    }
}

// ---------------------------------------------------------------------------
// Kernel T: transpose conv1_w for coalesced kW reads (validated)
// ---------------------------------------------------------------------------
__global__ void kT(const float* __restrict__ k1) {
    int i = blockIdx.x * 256 + threadIdx.x;
    if (i >= TAPS * WNN * CC) return;
    int tap = i / (WNN * CC);
    int rc  = i - tap * (WNN * CC);
    g_k1T[i] = k1[(size_t)rc * TAPS + tap];
}

// ---------------------------------------------------------------------------
// Kernel A: pooled depthwise stats -> downchannel logits (validated)
// ---------------------------------------------------------------------------
__global__ void kA(const float* __restrict__ x, const float* __restrict__ k1,
                   const float* __restrict__ dcw, const float* __restrict__ dcb) {
    int b   = blockIdx.x >> 4;
    int win = blockIdx.x & 15;
    int c   = threadIdx.x;
    int rb  = win >> 2, cb = win & 3;
    const float* xp = x + ((size_t)b * RR * RR) * CC + c;
    int base = (rb * WSZ) * RR + cb * WSZ;

    float T = 0.f, r0 = 0.f, r15 = 0.f, c0 = 0.f, c15 = 0.f;
    float e00 = 0.f, e0f = 0.f, ef0 = 0.f, eff = 0.f;
    for (int i = 0; i < 16; i++) {
        float rowacc = 0.f, vj0 = 0.f, vj15 = 0.f;
#pragma unroll
        for (int j = 0; j < 16; j++) {
            float v = xp[(size_t)(base + i * RR + j) * CC];
            rowacc += v;
            if (j == 0)  { c0  += v; vj0  = v; }
            if (j == 15) { c15 += v; vj15 = v; }
        }
        T += rowacc;
        if (i == 0)  { r0  = rowacc; e00 = vj0; e0f = vj15; }
        if (i == 15) { r15 = rowacc; ef0 = vj0; eff = vj15; }
    }

    float Rex[3] = { r15, 0.f, r0 };
    float Cex[3] = { c15, 0.f, c0 };
    const float* kp = k1 + (size_t)(win * CC + c) * TAPS;
    float pooled = 0.f;
#pragma unroll
    for (int p = 0; p < 3; p++) {
#pragma unroll
        for (int q = 0; q < 3; q++) {
            float corner = 0.f;
            if (p == 0 && q == 0) corner = eff;
            if (p == 0 && q == 2) corner = ef0;
            if (p == 2 && q == 0) corner = e0f;
            if (p == 2 && q == 2) corner = e00;
            float S = T - Rex[p] - Cex[q] + corner;
            pooled += kp[p * 3 + q] * S;
        }
    }
    pooled *= (1.f / 256.f);
    float contrib = pooled * dcw[win * CC + c];

    __shared__ float red[192];
    red[c] = contrib;
    __syncthreads();
    for (int s = 96; s >= 6; s >>= 1) {
        if (c < s) red[c] += red[c + s];
        __syncthreads();
    }
    if (c == 0) {
        float tot = red[0] + red[1] + red[2] + red[3] + red[4] + red[5];
        g_t[b * WNN + win] = tot + dcb[win];
    }
}

// ---------------------------------------------------------------------------
// Kernel W: fused MLP (per-block recompute) + Weff in mma B-fragment order.
// ---------------------------------------------------------------------------
__global__ void __launch_bounds__(192)
kW(const float* __restrict__ gkb, const float* __restrict__ fw,
   const float* __restrict__ l1w, const float* __restrict__ l1b,
   const float* __restrict__ l2w, const float* __restrict__ l2b,
   const float* __restrict__ gkw) {
    int n = blockIdx.x;          // cout
    int c = threadIdx.x;         // cin = k
    __shared__ float ts[64], hs[256];
    __shared__ float sw_[64], swg[64];

    if (c < 64) ts[c] = g_t[c];
    __syncthreads();
    for (int u = c; u < 256; u += 192) {
        int b = u >> 6, j = u & 63;
        float a = l1b[j];
#pragma unroll
        for (int s = 0; s < 16; s++) a += ts[b * 16 + s] * l1w[j * 16 + s];
        hs[u] = 0.5f * a * (1.f + erff(a * 0.70710678118654752f));
    }
    __syncthreads();
    if (c < 64) {
        int b = c >> 4, s = c & 15;
        float a = l2b[s];
#pragma unroll
        for (int j = 0; j < 64; j++) a += hs[b * 64 + j] * l2w[s * 64 + j];
        float wv = 1.f / (1.f + expf(-a));
        sw_[c] = wv;
        swg[c] = wv * gkw[s];
    }
    __syncthreads();

    float f[17];
    const float* fp = fw + (size_t)n * ((WNN + 1) * CC) + c;
#pragma unroll
    for (int s = 0; s < 17; s++) f[s] = fp[s * CC];
    float g0 = gkb[0];

    int cg  = c >> 5, k32 = c & 31;
    int wrd = ((n >> 3) * 4 + (k32 >> 3)) * 64 + (n & 7) * 8 +
              (k32 & 3) * 2 + ((k32 >> 2) & 1);

#pragma unroll 1
    for (int tap = 0; tap < 9; tap++) {
        float kv[16];
        const float* kt = g_k1T + (size_t)tap * WNN * CC + c;
#pragma unroll
        for (int s = 0; s < 16; s++) kv[s] = kt[s * CC];
#pragma unroll
        for (int b = 0; b < 4; b++) {
            float acc = 0.f, ga = g0;
#pragma unroll
            for (int s = 0; s < 16; s++) {
                acc = fmaf(sw_[b * 16 + s] * kv[s], f[s], acc);
                ga  = fmaf(swg[b * 16 + s], kv[s], ga);
            }
            acc = fmaf(ga, f[16], acc);
            g_WeffB[((size_t)(b * 9 + tap) * 6 + cg) * 6144 + wrd] =
                __uint_as_float(f2tf(acc));
        }
    }
}

// ---------------------------------------------------------------------------
// Kernel D: tf32 mma.sync implicit GEMM, 4 fat warps (warp = 64m x 48n).
// No smem, no barriers; A/B fragment-ordered in gmem. B reg-double-buffered;
// next chunk's A prefetched into L1 (warp 0) while current chunk computes.
// ---------------------------------------------------------------------------
__global__ void __launch_bounds__(128, 2)
kD(const float* __restrict__ fb, float* __restrict__ out) {
    int tid  = threadIdx.x;
    int lane = tid & 31;
    int wid  = tid >> 5;
    int b    = blockIdx.y;
    int mt   = blockIdx.x;             // image row

    const float* WB = g_WeffB + (size_t)b * TAPS * 6 * 6144;
    int wn = wid * 6;

    float acc[4][6][4];
#pragma unroll
    for (int mi = 0; mi < 4; mi++)
#pragma unroll
        for (int ni = 0; ni < 6; ni++)
#pragma unroll
            for (int r = 0; r < 4; r++) acc[mi][ni][r] = 0.f;

    uint32_t bfA[6][4][2], bfB[6][4][2];

    auto loadB = [&](int kc, uint32_t (&bf)[6][4][2]) {
        int tap = kc / 6, cg = kc - tap * 6;
        const float* src = WB + ((size_t)tap * 6 + cg) * 6144;
#pragma unroll
        for (int ni = 0; ni < 6; ni++)
#pragma unroll
            for (int ks = 0; ks < 4; ks++) {
                float2 v = *(const float2*)(src + ((wn + ni) * 4 + ks) * 64 + lane * 2);
                bf[ni][ks][0] = __float_as_uint(v.x);
                bf[ni][ks][1] = __float_as_uint(v.y);
            }
    };
    auto prefA = [&](int kc) {
        if (kc >= 54) return;
        int tap = kc / 6, cg = kc - tap * 6;
        int dy = tap / 3 - 1, dxi = tap % 3;
        int sy = mt + dy;
        if ((unsigned)sy >= RR) return;
        const char* p = (const char*)(g_xA +
            ((((size_t)b * 3 + dxi) * RR + sy) * 6 + cg) * 2048);
        asm volatile("prefetch.global.L1 [%0];" :: "l"(p + lane * 256));
        asm volatile("prefetch.global.L1 [%0];" :: "l"(p + lane * 256 + 128));
    };
    auto computeChunk = [&](int kc, uint32_t (&bf)[6][4][2]) {
        int tap = kc / 6, cg = kc - tap * 6;
        int dy = tap / 3 - 1, dxi = tap % 3;
        int sy = mt + dy;
        if ((unsigned)sy >= RR) return;          // zero A -> no contribution
        const float* base = g_xA +
            ((((size_t)b * 3 + dxi) * RR + sy) * 6 + cg) * 2048;
#pragma unroll
        for (int ks = 0; ks < 4; ks++) {
            uint32_t af[4][4];
#pragma unroll
            for (int mi = 0; mi < 4; mi++) {
                float4 v = *(const float4*)(base + (ks * 4 + mi) * 128 + lane * 4);
                af[mi][0] = __float_as_uint(v.x);
                af[mi][1] = __float_as_uint(v.y);
                af[mi][2] = __float_as_uint(v.z);
                af[mi][3] = __float_as_uint(v.w);
            }
#pragma unroll
            for (int mi = 0; mi < 4; mi++)
#pragma unroll
                for (int ni = 0; ni < 6; ni++)
                    mma_tf32(acc[mi][ni], af[mi], bf[ni][ks]);
        }
    };

    loadB(0, bfA);
#pragma unroll 1
    for (int it = 0; it < 27; it++) {
        int kc = it * 2;
        loadB(kc + 1, bfB);
        if (wid == 0) prefA(kc + 1);
        computeChunk(kc, bfA);
        if (kc + 2 < 54) loadB(kc + 2, bfA);
        if (wid == 0) prefA(kc + 2);
        computeChunk(kc + 1, bfB);
    }

    // ---- epilogue: +bias, STG.64 ----
#pragma unroll
    for (int ni = 0; ni < 6; ni++) {
        int co = wid * 48 + ni * 8 + (lane & 3) * 2;
        float bx = fb[co], by = fb[co + 1];
#pragma unroll
        for (int mi = 0; mi < 4; mi++) {
            int m0 = mt * 64 + mi * 16 + (lane >> 2);
            size_t o0 = ((size_t)b * RR * RR + m0) * CC + co;
            *(float2*)(out + o0) =
                make_float2(acc[mi][ni][0] + bx, acc[mi][ni][1] + by);
            *(float2*)(out + o0 + (size_t)8 * CC) =
                make_float2(acc[mi][ni][2] + bx, acc[mi][ni][3] + by);
        }
    }
}

// ---------------------------------------------------------------------------
extern "C" void kernel_launch(void* const* d_in, const int* in_sizes, int n_in,
                              void* d_out, int out_size) {
    const float* x   = (const float*)d_in[0];
    const float* k1  = (const float*)d_in[1];
    const float* dcw = (const float*)d_in[2];
    const float* dcb = (const float*)d_in[3];
    const float* l1w = (const float*)d_in[4];
    const float* l1b = (const float*)d_in[5];
    const float* l2w = (const float*)d_in[6];
    const float* l2b = (const float*)d_in[7];
    const float* gkw = (const float*)d_in[8];
    const float* gkb = (const float*)d_in[9];
    const float* fw  = (const float*)d_in[10];
    const float* fb  = (const float*)d_in[11];
    float* out = (float*)d_out;

    static cudaStream_t s1 = nullptr;
    static cudaEvent_t evF = nullptr, evJ = nullptr;
    if (s1 == nullptr) {
        cudaStreamCreateWithFlags(&s1, cudaStreamNonBlocking);
        cudaEventCreateWithFlags(&evF, cudaEventDisableTiming);
        cudaEventCreateWithFlags(&evJ, cudaEventDisableTiming);
    }

    // fork: side chain (kT -> kA -> kW) runs concurrently with kX
    cudaEventRecord(evF, 0);
    cudaStreamWaitEvent(s1, evF, 0);

    kT<<<(TAPS * WNN * CC + 255) / 256, 256, 0, s1>>>(k1);
    kA<<<BB * WNN, CC, 0, s1>>>(x, k1, dcw, dcb);
    kW<<<CC, CC, 0, s1>>>(gkb, fw, l1w, l1b, l2w, l2b, gkw);
    cudaEventRecord(evJ, s1);

    kX<<<dim3(RR, 3, BB), 256>>>(x);

    // join
    cudaStreamWaitEvent(0, evJ, 0);
    dim3 g(RR, BB);
    kD<<<g, 128>>>(fb, out);
}